// round 4
// baseline (speedup 1.0000x reference)
#include <cuda_runtime.h>

// out[b, l, i, j] = emission[b, l, j] + transition[i, j]
// B=32, L=512, T=64. Output = 256 MB fp32, HBM-write-bound.
//
// One warp per TWO (b,l) rows (8192 warps).
// Lane: j8 = lane & 7 (8-float j chunk), igrp = lane >> 3 (i mod 4).
// Emission chunks for both rows register-resident (loaded once).
// Each of 16 iterations: one transition chunk load (L1-resident) feeds
// two adds + two 1KB-contiguous warp stores. L1 load traffic per stored
// byte: 0.5x (was 1.0x).

__device__ __forceinline__ void ldg256(const float* p, float4& a, float4& b) {
    asm volatile("ld.global.nc.v8.f32 {%0,%1,%2,%3,%4,%5,%6,%7}, [%8];"
                 : "=f"(a.x), "=f"(a.y), "=f"(a.z), "=f"(a.w),
                   "=f"(b.x), "=f"(b.y), "=f"(b.z), "=f"(b.w)
                 : "l"(p));
}

__device__ __forceinline__ void stg256_cs(float* p, float4 a, float4 b) {
    asm volatile("st.global.cs.v8.f32 [%0], {%1,%2,%3,%4,%5,%6,%7,%8};"
                 :: "l"(p),
                    "f"(a.x), "f"(a.y), "f"(a.z), "f"(a.w),
                    "f"(b.x), "f"(b.y), "f"(b.z), "f"(b.w)
                 : "memory");
}

__global__ __launch_bounds__(256)
void CRF_53128745451552_kernel(const float* __restrict__ em,
                               const float* __restrict__ tr,
                               float* __restrict__ out) {
    int warp = (blockIdx.x * blockDim.x + threadIdx.x) >> 5;  // 0..8191
    int lane = threadIdx.x & 31;
    int j8   = lane & 7;    // j chunk (8 floats)
    int igrp = lane >> 3;   // i mod 4

    size_t bl0 = (size_t)warp * 2;   // two consecutive rows

    // Emission chunks for both rows: loaded once, reused 16x each.
    float4 ea0, ea1, eb0, eb1;
    ldg256(em + (bl0 << 6)        + (j8 << 3), ea0, ea1);
    ldg256(em + ((bl0 + 1) << 6)  + (j8 << 3), eb0, eb1);

    const float* tp = tr  + (igrp << 6) + (j8 << 3);
    float*       oa = out + (bl0 << 12)       + (igrp << 6) + (j8 << 3);
    float*       ob = out + ((bl0 + 1) << 12) + (igrp << 6) + (j8 << 3);

#pragma unroll 8
    for (int it = 0; it < 16; it++) {
        float4 t0, t1;
        ldg256(tp + it * 256, t0, t1);   // transition[it*4+igrp, j8*8..] (L1 hit)

        float4 r0, r1;
        r0.x = ea0.x + t0.x;  r0.y = ea0.y + t0.y;
        r0.z = ea0.z + t0.z;  r0.w = ea0.w + t0.w;
        r1.x = ea1.x + t1.x;  r1.y = ea1.y + t1.y;
        r1.z = ea1.z + t1.z;  r1.w = ea1.w + t1.w;
        stg256_cs(oa + it * 256, r0, r1);

        float4 s0, s1;
        s0.x = eb0.x + t0.x;  s0.y = eb0.y + t0.y;
        s0.z = eb0.z + t0.z;  s0.w = eb0.w + t0.w;
        s1.x = eb1.x + t1.x;  s1.y = eb1.y + t1.y;
        s1.z = eb1.z + t1.z;  s1.w = eb1.w + t1.w;
        stg256_cs(ob + it * 256, s0, s1);
    }
}

extern "C" void kernel_launch(void* const* d_in, const int* in_sizes, int n_in,
                              void* d_out, int out_size) {
    const float* em = (const float*)d_in[0];   // emission [32, 512, 64] fp32
    const float* tr = (const float*)d_in[1];   // transition [64, 64] fp32
    float* out = (float*)d_out;

    // 16384 rows / 2 rows-per-warp = 8192 warps; 8 warps/block -> 1024 blocks.
    const int threads = 256;
    const int blocks  = 1024;
    CRF_53128745451552_kernel<<<blocks, threads>>>(em, tr, out);
}